// round 7
// baseline (speedup 1.0000x reference)
#include <cuda_runtime.h>
#include <math.h>

#define NNODES 50000
#define NEDGES 800000

// ---------------- scratch (static __device__ — no allocations, zero-init) ----------------
__device__ __align__(16) float g_xl[NNODES * 128];
__device__ __align__(16) float g_xr[NNODES * 128];
__device__ __align__(16) float g_res[NNODES * 128];
__device__ __align__(16) float g_h1[NNODES * 32];
__device__ __align__(16) float g_h2[NNODES * 128];
__device__ __align__(16) float g_eaP[NEDGES * 8];    // edge_attr permuted to CSR order
__device__ int g_deg[NNODES];                        // zero at start of every replay
__device__ int g_rowptr[NNODES + 1];
__device__ int g_wptr[NNODES];
__device__ int g_colsrc[NEDGES];

// ---------------- CSR build ----------------
__global__ void hist_kernel(const int* __restrict__ dst, int* __restrict__ deg, int e) {
    int i = blockIdx.x * blockDim.x + threadIdx.x;
    if (i < e) atomicAdd(&deg[dst[i]], 1);
}

// single-block exclusive scan; ALSO zeroes deg (restores invariant for next replay)
__global__ void scan_kernel(int* __restrict__ deg, int* __restrict__ rowptr,
                            int* __restrict__ wptr, int n, int e) {
    __shared__ int warpsum[32];
    __shared__ int s_carry;
    int tid = threadIdx.x, lane = tid & 31, wid = tid >> 5;
    if (tid == 0) s_carry = 0;
    __syncthreads();
    for (int base = 0; base < n; base += 1024) {
        int i = base + tid;
        int v = (i < n) ? deg[i] : 0;
        if (i < n) deg[i] = 0;
        int x = v;
        #pragma unroll
        for (int off = 1; off < 32; off <<= 1) {
            int t = __shfl_up_sync(0xffffffffu, x, off);
            if (lane >= off) x += t;
        }
        if (lane == 31) warpsum[wid] = x;
        __syncthreads();
        if (wid == 0) {
            int y = warpsum[lane];
            #pragma unroll
            for (int off = 1; off < 32; off <<= 1) {
                int t = __shfl_up_sync(0xffffffffu, y, off);
                if (lane >= off) y += t;
            }
            warpsum[lane] = y;
        }
        __syncthreads();
        int excl = x - v + (wid > 0 ? warpsum[wid - 1] : 0) + s_carry;
        if (i < n) { rowptr[i] = excl; wptr[i] = excl; }
        __syncthreads();
        if (tid == 0) s_carry += warpsum[31];
        __syncthreads();
    }
    if (tid == 0) rowptr[n] = e;
}

// scatter src ids AND permute edge_attr into CSR order (eaP)
__global__ void scatter_kernel(const int* __restrict__ src, const int* __restrict__ dst,
                               const float* __restrict__ eattr, int* __restrict__ wptr,
                               int* __restrict__ colsrc, float* __restrict__ eaP, int e) {
    int i = blockIdx.x * blockDim.x + threadIdx.x;
    if (i >= e) return;
    int d = dst[i];
    int p = atomicAdd(&wptr[d], 1);
    colsrc[p] = src[i];
    float4 a = *(const float4*)(eattr + (size_t)i * 8);
    float4 b = *(const float4*)(eattr + (size_t)i * 8 + 4);
    *(float4*)(eaP + (size_t)p * 8) = a;
    *(float4*)(eaP + (size_t)p * 8 + 4) = b;
}

// ---------------- dense GEMM: up to NW weight sets sharing A ----------------
template <int K, int DOUT, int NW, int ROWS, int KC>
__global__ void gemm_multi(const float* __restrict__ A,
                           const float* __restrict__ W0, const float* __restrict__ b0, float* __restrict__ O0,
                           const float* __restrict__ W1, const float* __restrict__ b1, float* __restrict__ O1,
                           const float* __restrict__ W2, const float* __restrict__ b2, float* __restrict__ O2,
                           int n) {
    constexpr int COLS = DOUT * NW;
    constexpr int TX = COLS / 4;
    constexpr int TY = ROWS / 4;
    constexpr int NT = TX * TY;
    constexpr bool STAGE = (K * COLS * 4 <= 40960);
    constexpr int SWSZ = STAGE ? K * COLS : 1;
    __shared__ float sW[SWSZ];
    __shared__ float sA[KC][ROWS + 1];
    int tid = threadIdx.x;
    if (STAGE) {
        for (int idx = tid; idx < K * DOUT; idx += NT) {
            int k = idx / DOUT, c = idx % DOUT;
            sW[k * COLS + c] = W0[idx];
            if (NW > 1) sW[k * COLS + DOUT + c] = W1[idx];
            if (NW > 2) sW[k * COLS + 2 * DOUT + c] = W2[idx];
        }
    }
    int tx = tid % TX, ty = tid / TX;
    int cg = tx * 4;
    int which = cg / DOUT, col = cg % DOUT;
    const float* bb = (which == 0) ? b0 : (which == 1) ? b1 : b2;
    const float* Wp = (which == 0) ? W0 : (which == 1) ? W1 : W2;
    int row0 = blockIdx.x * ROWS;

    float acc[4][4];
    #pragma unroll
    for (int i = 0; i < 4; i++)
        #pragma unroll
        for (int j = 0; j < 4; j++) acc[i][j] = bb[col + j];

    for (int kc0 = 0; kc0 < K; kc0 += KC) {
        __syncthreads();
        for (int idx = tid; idx < ROWS * KC; idx += NT) {
            int r = idx / KC, k = idx % KC;
            int gr = row0 + r;
            sA[k][r] = (gr < n) ? A[(size_t)gr * K + kc0 + k] : 0.f;
        }
        __syncthreads();
        #pragma unroll
        for (int k = 0; k < KC; k++) {
            float4 rb;
            if (STAGE) rb = *(const float4*)&sW[(kc0 + k) * COLS + cg];
            else       rb = __ldg((const float4*)&Wp[(size_t)(kc0 + k) * DOUT + col]);
            float ra0 = sA[k][ty * 4 + 0];
            float ra1 = sA[k][ty * 4 + 1];
            float ra2 = sA[k][ty * 4 + 2];
            float ra3 = sA[k][ty * 4 + 3];
            acc[0][0] = fmaf(ra0, rb.x, acc[0][0]); acc[0][1] = fmaf(ra0, rb.y, acc[0][1]);
            acc[0][2] = fmaf(ra0, rb.z, acc[0][2]); acc[0][3] = fmaf(ra0, rb.w, acc[0][3]);
            acc[1][0] = fmaf(ra1, rb.x, acc[1][0]); acc[1][1] = fmaf(ra1, rb.y, acc[1][1]);
            acc[1][2] = fmaf(ra1, rb.z, acc[1][2]); acc[1][3] = fmaf(ra1, rb.w, acc[1][3]);
            acc[2][0] = fmaf(ra2, rb.x, acc[2][0]); acc[2][1] = fmaf(ra2, rb.y, acc[2][1]);
            acc[2][2] = fmaf(ra2, rb.z, acc[2][2]); acc[2][3] = fmaf(ra2, rb.w, acc[2][3]);
            acc[3][0] = fmaf(ra3, rb.x, acc[3][0]); acc[3][1] = fmaf(ra3, rb.y, acc[3][1]);
            acc[3][2] = fmaf(ra3, rb.z, acc[3][2]); acc[3][3] = fmaf(ra3, rb.w, acc[3][3]);
        }
    }
    float* O = (which == 0) ? O0 : (which == 1) ? O1 : O2;
    #pragma unroll
    for (int i = 0; i < 4; i++) {
        int gr = row0 + ty * 4 + i;
        if (gr < n)
            *(float4*)&O[(size_t)gr * DOUT + col] =
                make_float4(acc[i][0], acc[i][1], acc[i][2], acc[i][3]);
    }
}

// ---------------- fused GATv2 edge pass ----------------
// SW warps per dst; each warp owns channels ch0 = sub*32*VEC + lane*VEC .. +VEC.
// Self-loop is fused: edge-attr sum accumulated in-loop, mean applied as a last
// virtual edge (matches reference softmax up to fp reordering).
//   layer1: VEC=1,SW=1,GROUP=8   (D=32,  H=4)
//   layer2: VEC=2,SW=2,GROUP=16  (D=128, H=4; head = 16-lane group)
//   layer3: VEC=1,SW=1,GROUP=32  (D=32,  H=1)
template <int VEC, int SW, int GROUP, bool RELU>
__global__ __launch_bounds__(256) void agg_kernel(
    const float* __restrict__ xl, const float* __restrict__ xr,
    const float* __restrict__ eaP, const float* __restrict__ We,
    const float* __restrict__ att, const float* __restrict__ bias,
    const float* __restrict__ pre, const int* __restrict__ rowptr,
    const int* __restrict__ colsrc, float* __restrict__ out, int n) {
    constexpr int D = 32 * VEC * SW;
    constexpr int DPB = 8 / SW;                 // dsts per 256-thread block
    int tid = threadIdx.x, lane = tid & 31, wid = tid >> 5;
    int dst = blockIdx.x * DPB + wid / SW;
    int sub = (SW > 1) ? (wid % SW) : 0;
    if (dst >= n) return;

    const int ch0 = sub * 32 * VEC + lane * VEC;

    // We in registers (once per warp lifetime)
    float rWe[8][VEC];
    #pragma unroll
    for (int q = 0; q < 8; q++) {
        if (VEC == 2) {
            float2 w = __ldg((const float2*)(We + q * D + ch0));
            rWe[q][0] = w.x; rWe[q][1] = w.y;
        } else {
            rWe[q][0] = __ldg(We + q * D + ch0);
        }
    }

    float attv[VEC], xrv[VEC], xld[VEC], num[VEC];
    float den = 0.f;
    float easum[8];
    #pragma unroll
    for (int q = 0; q < 8; q++) easum[q] = 0.f;
    if (VEC == 2) {
        float2 a = __ldg((const float2*)(att + ch0));
        attv[0] = a.x; attv[1] = a.y;
        float2 r = *(const float2*)(xr + (size_t)dst * D + ch0);
        xrv[0] = r.x; xrv[1] = r.y;
        float2 l = *(const float2*)(xl + (size_t)dst * D + ch0);
        xld[0] = l.x; xld[1] = l.y;
    } else {
        attv[0] = __ldg(att + ch0);
        xrv[0] = xr[(size_t)dst * D + ch0];
        xld[0] = xl[(size_t)dst * D + ch0];
    }
    #pragma unroll
    for (int v = 0; v < VEC; v++) num[v] = 0.f;

    auto ldX = [&](float* d, const float* p) {
        if (VEC == 2) {
            float2 t = *(const float2*)p;
            d[0] = t.x; d[1] = t.y;
        } else d[0] = p[0];
    };
    auto ldE = [&](float* d, const float* p) {
        float4 a = *(const float4*)p;
        float4 b = *(const float4*)(p + 4);
        d[0] = a.x; d[1] = a.y; d[2] = a.z; d[3] = a.w;
        d[4] = b.x; d[5] = b.y; d[6] = b.z; d[7] = b.w;
    };
    auto body = [&](const float* xv, const float* ev, bool accum_ea) {
        float m[VEC];
        #pragma unroll
        for (int v = 0; v < VEC; v++) m[v] = 0.f;
        #pragma unroll
        for (int q = 0; q < 8; q++) {
            #pragma unroll
            for (int v = 0; v < VEC; v++)
                m[v] = fmaf(ev[q], rWe[q][v], m[v]);
            if (accum_ea) easum[q] += ev[q];
        }
        float p = 0.f;
        #pragma unroll
        for (int v = 0; v < VEC; v++) {
            float t = m[v] + xv[v] + xrv[v];
            float s = fmaxf(t, 0.f) + 0.2f * fminf(t, 0.f);
            p = fmaf(s, attv[v], p);
        }
        #pragma unroll
        for (int off = GROUP / 2; off > 0; off >>= 1)
            p += __shfl_xor_sync(0xffffffffu, p, off);
        float w = __expf(p);
        #pragma unroll
        for (int v = 0; v < VEC; v++) num[v] = fmaf(w, xv[v], num[v]);
        den += w;
    };

    int rs = rowptr[dst], re = rowptr[dst + 1];

    // depth-3 pipeline, compile-time slots
    float x0[VEC], e0[8], x1[VEC], e1[8], x2[VEC], e2[8];
#define PREF(X, EA, IDX) do { int kk = (IDX); if (kk < re) { \
        int s_ = colsrc[kk]; \
        ldE(EA, eaP + (size_t)kk * 8); \
        ldX(X, xl + (size_t)s_ * D + ch0); } } while (0)
    PREF(x0, e0, rs);
    PREF(x1, e1, rs + 1);
    PREF(x2, e2, rs + 2);
    int k = rs;
    while (k < re) {
        {
            float cx[VEC], ce[8];
            #pragma unroll
            for (int v = 0; v < VEC; v++) cx[v] = x0[v];
            #pragma unroll
            for (int q = 0; q < 8; q++) ce[q] = e0[q];
            PREF(x0, e0, k + 3);
            body(cx, ce, true);
        }
        if (++k >= re) break;
        {
            float cx[VEC], ce[8];
            #pragma unroll
            for (int v = 0; v < VEC; v++) cx[v] = x1[v];
            #pragma unroll
            for (int q = 0; q < 8; q++) ce[q] = e1[q];
            PREF(x1, e1, k + 3);
            body(cx, ce, true);
        }
        if (++k >= re) break;
        {
            float cx[VEC], ce[8];
            #pragma unroll
            for (int v = 0; v < VEC; v++) cx[v] = x2[v];
            #pragma unroll
            for (int q = 0; q < 8; q++) ce[q] = e2[q];
            PREF(x2, e2, k + 3);
            body(cx, ce, true);
        }
        ++k;
    }
#undef PREF

    // fused self loop: mean edge-attr of incoming edges
    {
        float inv = 1.0f / (float)((re - rs) > 0 ? (re - rs) : 1);
        float se[8];
        #pragma unroll
        for (int q = 0; q < 8; q++) se[q] = easum[q] * inv;
        body(xld, se, false);
    }

    float res[VEC];
    #pragma unroll
    for (int v = 0; v < VEC; v++) {
        float val = num[v] / den;
        if (bias) val += bias[ch0 + v];
        if (pre) val += pre[(size_t)dst * D + ch0 + v];
        if (RELU) val = fmaxf(val, 0.f);
        res[v] = val;
    }
    if (VEC == 2)
        *(float2*)&out[(size_t)dst * D + ch0] = make_float2(res[0], res[1]);
    else
        out[(size_t)dst * D + ch0] = res[0];
}

// ---------------- host launcher ----------------
extern "C" void kernel_launch(void* const* d_in, const int* in_sizes, int n_in,
                              void* d_out, int out_size) {
    const float* x     = (const float*)d_in[0];
    const int*   eidx  = (const int*)d_in[1];
    const float* eattr = (const float*)d_in[2];
    const float* Wl1 = (const float*)d_in[3];
    const float* bl1 = (const float*)d_in[4];
    const float* Wr1 = (const float*)d_in[5];
    const float* br1 = (const float*)d_in[6];
    const float* We1 = (const float*)d_in[7];
    const float* att1 = (const float*)d_in[8];
    const float* b1 = (const float*)d_in[9];
    const float* Wl2 = (const float*)d_in[10];
    const float* bl2 = (const float*)d_in[11];
    const float* Wr2 = (const float*)d_in[12];
    const float* br2 = (const float*)d_in[13];
    const float* We2 = (const float*)d_in[14];
    const float* att2 = (const float*)d_in[15];
    const float* b2 = (const float*)d_in[16];
    const float* Rw2 = (const float*)d_in[17];
    const float* Wl3 = (const float*)d_in[18];
    const float* bl3 = (const float*)d_in[19];
    const float* Wr3 = (const float*)d_in[20];
    const float* br3 = (const float*)d_in[21];
    const float* We3 = (const float*)d_in[22];
    const float* att3 = (const float*)d_in[23];
    const float* b3 = (const float*)d_in[24];

    int Nn = in_sizes[0] / 16;   // 50000
    int Ee = in_sizes[1] / 2;    // 800000
    const int* srcp = eidx;
    const int* dstp = eidx + Ee;

    float *xl, *xr, *res, *h1, *h2, *eaP;
    int *deg, *rowptr, *wptr, *colsrc;
    cudaGetSymbolAddress((void**)&xl, g_xl);
    cudaGetSymbolAddress((void**)&xr, g_xr);
    cudaGetSymbolAddress((void**)&res, g_res);
    cudaGetSymbolAddress((void**)&h1, g_h1);
    cudaGetSymbolAddress((void**)&h2, g_h2);
    cudaGetSymbolAddress((void**)&eaP, g_eaP);
    cudaGetSymbolAddress((void**)&deg, g_deg);
    cudaGetSymbolAddress((void**)&rowptr, g_rowptr);
    cudaGetSymbolAddress((void**)&wptr, g_wptr);
    cudaGetSymbolAddress((void**)&colsrc, g_colsrc);

    // launch 0: layer-1 GEMM (independent of CSR) — keeps agg1 at capture slot 4
    gemm_multi<16, 32, 2, 32, 16><<<(Nn + 31) / 32, 128>>>(
        x, Wl1, bl1, xl, Wr1, br1, xr, nullptr, nullptr, nullptr, Nn);

    // launches 1-3: CSR build (deg starts zero; scan re-zeroes it for next replay)
    hist_kernel<<<(Ee + 255) / 256, 256>>>(dstp, deg, Ee);
    scan_kernel<<<1, 1024>>>(deg, rowptr, wptr, Nn, Ee);
    scatter_kernel<<<(Ee + 255) / 256, 256>>>(srcp, dstp, eattr, wptr, colsrc, eaP, Ee);

    // launch 4 (ncu capture slot): layer-1 edge pass
    agg_kernel<1, 1, 8, true><<<(Nn + 7) / 8, 256>>>(
        xl, xr, eaP, We1, att1, b1, nullptr, rowptr, colsrc, h1, Nn);

    // layer 2: fused 3x GEMM + edge pass (2 warps per dst)
    gemm_multi<32, 128, 3, 16, 32><<<(Nn + 15) / 16, 384>>>(
        h1, Wl2, bl2, xl, Wr2, br2, xr, Rw2, b2, res, Nn);
    agg_kernel<2, 2, 16, true><<<(Nn + 3) / 4, 256>>>(
        xl, xr, eaP, We2, att2, nullptr, res, rowptr, colsrc, h2, Nn);

    // layer 3
    gemm_multi<128, 32, 2, 32, 32><<<(Nn + 31) / 32, 128>>>(
        h2, Wl3, bl3, xl, Wr3, br3, xr, nullptr, nullptr, nullptr, Nn);
    agg_kernel<1, 1, 32, false><<<(Nn + 7) / 8, 256>>>(
        xl, xr, eaP, We3, att3, b3, nullptr, rowptr, colsrc, (float*)d_out, Nn);
}

// round 8
// speedup vs baseline: 1.3278x; 1.3278x over previous
#include <cuda_runtime.h>
#include <math.h>

#define NNODES 50000
#define NEDGES 800000

// ---------------- scratch (static __device__ — no allocations) ----------------
__device__ __align__(16) float g_xl[NNODES * 128];
__device__ __align__(16) float g_xr[NNODES * 128];
__device__ __align__(16) float g_res[NNODES * 128];
__device__ __align__(16) float g_h1[NNODES * 32];
__device__ __align__(16) float g_h2[NNODES * 128];
__device__ __align__(16) float g_loop[NNODES * 8];
__device__ __align__(16) float g_eaP[NEDGES * 8];    // edge_attr permuted to CSR order
__device__ int g_deg[NNODES];
__device__ int g_rowptr[NNODES + 1];
__device__ int g_wptr[NNODES];
__device__ int g_bsum[1024];
__device__ int g_colsrc[NEDGES];

// ---------------- CSR build ----------------
__global__ void hist_kernel(const int* __restrict__ dst, int* __restrict__ deg, int e) {
    int i = blockIdx.x * blockDim.x + threadIdx.x;
    if (i < e) atomicAdd(&deg[dst[i]], 1);
}

__global__ void blocksum_kernel(const int* __restrict__ deg, int* __restrict__ bsum, int n) {
    __shared__ int sh[32];
    int tid = threadIdx.x, lane = tid & 31, wid = tid >> 5;
    int i = blockIdx.x * 1024 + tid;
    int v = (i < n) ? deg[i] : 0;
    #pragma unroll
    for (int off = 16; off > 0; off >>= 1) v += __shfl_xor_sync(0xffffffffu, v, off);
    if (lane == 0) sh[wid] = v;
    __syncthreads();
    if (wid == 0) {
        int x = sh[lane];
        #pragma unroll
        for (int off = 16; off > 0; off >>= 1) x += __shfl_xor_sync(0xffffffffu, x, off);
        if (lane == 0) bsum[blockIdx.x] = x;
    }
}

__global__ void scanpart_kernel(int* __restrict__ b, int g) {
    __shared__ int ws[32];
    int tid = threadIdx.x, lane = tid & 31, wid = tid >> 5;
    int v = (tid < g) ? b[tid] : 0;
    int x = v;
    #pragma unroll
    for (int off = 1; off < 32; off <<= 1) {
        int t = __shfl_up_sync(0xffffffffu, x, off);
        if (lane >= off) x += t;
    }
    if (lane == 31) ws[wid] = x;
    __syncthreads();
    if (wid == 0) {
        int y = ws[lane];
        #pragma unroll
        for (int off = 1; off < 32; off <<= 1) {
            int t = __shfl_up_sync(0xffffffffu, y, off);
            if (lane >= off) y += t;
        }
        ws[lane] = y;
    }
    __syncthreads();
    int excl = x - v + (wid > 0 ? ws[wid - 1] : 0);
    if (tid < g) b[tid] = excl;
}

__global__ void scanfinal_kernel(const int* __restrict__ deg, const int* __restrict__ bsum,
                                 int* __restrict__ rowptr, int* __restrict__ wptr,
                                 int n, int e) {
    __shared__ int ws[32];
    int tid = threadIdx.x, lane = tid & 31, wid = tid >> 5;
    int i = blockIdx.x * 1024 + tid;
    int v = (i < n) ? deg[i] : 0;
    int x = v;
    #pragma unroll
    for (int off = 1; off < 32; off <<= 1) {
        int t = __shfl_up_sync(0xffffffffu, x, off);
        if (lane >= off) x += t;
    }
    if (lane == 31) ws[wid] = x;
    __syncthreads();
    if (wid == 0) {
        int y = ws[lane];
        #pragma unroll
        for (int off = 1; off < 32; off <<= 1) {
            int t = __shfl_up_sync(0xffffffffu, y, off);
            if (lane >= off) y += t;
        }
        ws[lane] = y;
    }
    __syncthreads();
    int excl = x - v + (wid > 0 ? ws[wid - 1] : 0) + bsum[blockIdx.x];
    if (i < n) { rowptr[i] = excl; wptr[i] = excl; }
    if (blockIdx.x == 0 && tid == 0) rowptr[n] = e;
}

// scatter src ids AND permute edge_attr into CSR order (eaP)
__global__ void scatter_kernel(const int* __restrict__ src, const int* __restrict__ dst,
                               const float* __restrict__ eattr, int* __restrict__ wptr,
                               int* __restrict__ colsrc, float* __restrict__ eaP, int e) {
    int i = blockIdx.x * blockDim.x + threadIdx.x;
    if (i >= e) return;
    int d = dst[i];
    int p = atomicAdd(&wptr[d], 1);
    colsrc[p] = src[i];
    float4 a = *(const float4*)(eattr + (size_t)i * 8);
    float4 b = *(const float4*)(eattr + (size_t)i * 8 + 4);
    *(float4*)(eaP + (size_t)p * 8) = a;
    *(float4*)(eaP + (size_t)p * 8 + 4) = b;
}

// loop-attr mean from CSR (coalesced sequential reads of eaP), divide folded in
__global__ void loopattr_kernel(const int* __restrict__ rowptr, const float* __restrict__ eaP,
                                float* __restrict__ loopv, int n) {
    int tid = blockIdx.x * blockDim.x + threadIdx.x;
    int g = tid >> 3, c = tid & 7;
    if (g >= n) return;
    int rs = rowptr[g], re = rowptr[g + 1];
    float s = 0.f;
    for (int k = rs; k < re; k++) s += eaP[(size_t)k * 8 + c];
    int d = re - rs;
    loopv[g * 8 + c] = s / (float)(d > 0 ? d : 1);
}

// ---------------- dense GEMM: up to NW weight sets sharing A ----------------
template <int K, int DOUT, int NW, int ROWS, int KC>
__global__ void gemm_multi(const float* __restrict__ A,
                           const float* __restrict__ W0, const float* __restrict__ b0, float* __restrict__ O0,
                           const float* __restrict__ W1, const float* __restrict__ b1, float* __restrict__ O1,
                           const float* __restrict__ W2, const float* __restrict__ b2, float* __restrict__ O2,
                           int n) {
    constexpr int COLS = DOUT * NW;
    constexpr int TX = COLS / 4;
    constexpr int TY = ROWS / 4;
    constexpr int NT = TX * TY;
    constexpr bool STAGE = (K * COLS * 4 <= 40960);
    constexpr int SWSZ = STAGE ? K * COLS : 1;
    __shared__ float sW[SWSZ];
    __shared__ float sA[KC][ROWS + 1];
    int tid = threadIdx.x;
    if (STAGE) {
        for (int idx = tid; idx < K * DOUT; idx += NT) {
            int k = idx / DOUT, c = idx % DOUT;
            sW[k * COLS + c] = W0[idx];
            if (NW > 1) sW[k * COLS + DOUT + c] = W1[idx];
            if (NW > 2) sW[k * COLS + 2 * DOUT + c] = W2[idx];
        }
    }
    int tx = tid % TX, ty = tid / TX;
    int cg = tx * 4;
    int which = cg / DOUT, col = cg % DOUT;
    const float* bb = (which == 0) ? b0 : (which == 1) ? b1 : b2;
    const float* Wp = (which == 0) ? W0 : (which == 1) ? W1 : W2;
    int row0 = blockIdx.x * ROWS;

    float acc[4][4];
    #pragma unroll
    for (int i = 0; i < 4; i++)
        #pragma unroll
        for (int j = 0; j < 4; j++) acc[i][j] = bb[col + j];

    for (int kc0 = 0; kc0 < K; kc0 += KC) {
        __syncthreads();
        for (int idx = tid; idx < ROWS * KC; idx += NT) {
            int r = idx / KC, k = idx % KC;
            int gr = row0 + r;
            sA[k][r] = (gr < n) ? A[(size_t)gr * K + kc0 + k] : 0.f;
        }
        __syncthreads();
        #pragma unroll
        for (int k = 0; k < KC; k++) {
            float4 rb;
            if (STAGE) rb = *(const float4*)&sW[(kc0 + k) * COLS + cg];
            else       rb = __ldg((const float4*)&Wp[(size_t)(kc0 + k) * DOUT + col]);
            float ra0 = sA[k][ty * 4 + 0];
            float ra1 = sA[k][ty * 4 + 1];
            float ra2 = sA[k][ty * 4 + 2];
            float ra3 = sA[k][ty * 4 + 3];
            acc[0][0] = fmaf(ra0, rb.x, acc[0][0]); acc[0][1] = fmaf(ra0, rb.y, acc[0][1]);
            acc[0][2] = fmaf(ra0, rb.z, acc[0][2]); acc[0][3] = fmaf(ra0, rb.w, acc[0][3]);
            acc[1][0] = fmaf(ra1, rb.x, acc[1][0]); acc[1][1] = fmaf(ra1, rb.y, acc[1][1]);
            acc[1][2] = fmaf(ra1, rb.z, acc[1][2]); acc[1][3] = fmaf(ra1, rb.w, acc[1][3]);
            acc[2][0] = fmaf(ra2, rb.x, acc[2][0]); acc[2][1] = fmaf(ra2, rb.y, acc[2][1]);
            acc[2][2] = fmaf(ra2, rb.z, acc[2][2]); acc[2][3] = fmaf(ra2, rb.w, acc[2][3]);
            acc[3][0] = fmaf(ra3, rb.x, acc[3][0]); acc[3][1] = fmaf(ra3, rb.y, acc[3][1]);
            acc[3][2] = fmaf(ra3, rb.z, acc[3][2]); acc[3][3] = fmaf(ra3, rb.w, acc[3][3]);
        }
    }
    float* O = (which == 0) ? O0 : (which == 1) ? O1 : O2;
    #pragma unroll
    for (int i = 0; i < 4; i++) {
        int gr = row0 + ty * 4 + i;
        if (gr < n)
            *(float4*)&O[(size_t)gr * DOUT + col] =
                make_float4(acc[i][0], acc[i][1], acc[i][2], acc[i][3]);
    }
}

// ---------------- fused GATv2 edge pass ----------------
// SW warps per dst; warp owns channels ch0 = sub*32*VEC + lane*VEC.
//   layer1: VEC=1,SW=1,GROUP=8   (D=32,  H=4; head = 8-lane group)
//   layer2: VEC=2,SW=2,GROUP=16  (D=128, H=4; head = 16-lane group)
//   layer3: VEC=1,SW=1,GROUP=32  (D=32,  H=1)
// depth-2 software pipeline with compile-time slots (R6-proven structure).
template <int VEC, int SW, int GROUP, bool RELU>
__global__ __launch_bounds__(256) void agg_kernel(
    const float* __restrict__ xl, const float* __restrict__ xr,
    const float* __restrict__ eaP, const float* __restrict__ We,
    const float* __restrict__ att, const float* __restrict__ bias,
    const float* __restrict__ pre, const int* __restrict__ rowptr,
    const int* __restrict__ colsrc, const float* __restrict__ loopattr,
    float* __restrict__ out, int n) {
    constexpr int D = 32 * VEC * SW;
    constexpr int DPB = 8 / SW;               // dsts per 256-thread block
    int tid = threadIdx.x, lane = tid & 31, wid = tid >> 5;
    int dst = blockIdx.x * DPB + wid / SW;
    int sub = (SW > 1) ? (wid % SW) : 0;
    if (dst >= n) return;

    const int ch0 = sub * 32 * VEC + lane * VEC;

    // We in registers: loaded once per warp lifetime
    float rWe[8][VEC];
    #pragma unroll
    for (int q = 0; q < 8; q++) {
        if (VEC == 2) {
            float2 w = __ldg((const float2*)(We + q * D + ch0));
            rWe[q][0] = w.x; rWe[q][1] = w.y;
        } else {
            rWe[q][0] = __ldg(We + q * D + ch0);
        }
    }

    float attv[VEC], xrv[VEC], num[VEC];
    float den = 0.f;
    if (VEC == 2) {
        float2 a = __ldg((const float2*)(att + ch0));
        attv[0] = a.x; attv[1] = a.y;
        float2 r = *(const float2*)(xr + (size_t)dst * D + ch0);
        xrv[0] = r.x; xrv[1] = r.y;
    } else {
        attv[0] = __ldg(att + ch0);
        xrv[0] = xr[(size_t)dst * D + ch0];
    }
    #pragma unroll
    for (int v = 0; v < VEC; v++) num[v] = 0.f;

    auto ldX = [&](float* d, const float* p) {
        if (VEC == 2) {
            float2 t = *(const float2*)p;
            d[0] = t.x; d[1] = t.y;
        } else d[0] = p[0];
    };
    auto ldE = [&](float* d, const float* p) {
        float4 a = *(const float4*)p;
        float4 b = *(const float4*)(p + 4);
        d[0] = a.x; d[1] = a.y; d[2] = a.z; d[3] = a.w;
        d[4] = b.x; d[5] = b.y; d[6] = b.z; d[7] = b.w;
    };
    auto body = [&](const float* xv, const float* ev) {
        float m[VEC];
        #pragma unroll
        for (int v = 0; v < VEC; v++) m[v] = 0.f;
        #pragma unroll
        for (int q = 0; q < 8; q++)
            #pragma unroll
            for (int v = 0; v < VEC; v++)
                m[v] = fmaf(ev[q], rWe[q][v], m[v]);
        float p = 0.f;
        #pragma unroll
        for (int v = 0; v < VEC; v++) {
            float t = m[v] + xv[v] + xrv[v];
            float s = fmaxf(t, 0.f) + 0.2f * fminf(t, 0.f);
            p = fmaf(s, attv[v], p);
        }
        #pragma unroll
        for (int off = GROUP / 2; off > 0; off >>= 1)
            p += __shfl_xor_sync(0xffffffffu, p, off);
        float w = __expf(p);
        #pragma unroll
        for (int v = 0; v < VEC; v++) num[v] = fmaf(w, xv[v], num[v]);
        den += w;
    };

    int rs = rowptr[dst], re = rowptr[dst + 1];

    // depth-2 pipeline, compile-time slot indices
    float px0[VEC], pe0[8], px1[VEC], pe1[8];
    if (rs < re) {
        int s = colsrc[rs];
        ldE(pe0, eaP + (size_t)rs * 8);
        ldX(px0, xl + (size_t)s * D + ch0);
    }
    if (rs + 1 < re) {
        int s = colsrc[rs + 1];
        ldE(pe1, eaP + (size_t)(rs + 1) * 8);
        ldX(px1, xl + (size_t)s * D + ch0);
    }
    {   // self loop (its loads overlap the prefetches above)
        float sx[VEC], se[8];
        ldX(sx, xl + (size_t)dst * D + ch0);
        ldE(se, loopattr + (size_t)dst * 8);
        body(sx, se);
    }
    int k = rs;
    while (k < re) {
        {   // consume slot 0
            float cx[VEC], ce[8];
            #pragma unroll
            for (int v = 0; v < VEC; v++) cx[v] = px0[v];
            #pragma unroll
            for (int q = 0; q < 8; q++) ce[q] = pe0[q];
            if (k + 2 < re) {
                int s = colsrc[k + 2];
                ldE(pe0, eaP + (size_t)(k + 2) * 8);
                ldX(px0, xl + (size_t)s * D + ch0);
            }
            body(cx, ce);
        }
        k++;
        if (k >= re) break;
        {   // consume slot 1
            float cx[VEC], ce[8];
            #pragma unroll
            for (int v = 0; v < VEC; v++) cx[v] = px1[v];
            #pragma unroll
            for (int q = 0; q < 8; q++) ce[q] = pe1[q];
            if (k + 2 < re) {
                int s = colsrc[k + 2];
                ldE(pe1, eaP + (size_t)(k + 2) * 8);
                ldX(px1, xl + (size_t)s * D + ch0);
            }
            body(cx, ce);
        }
        k++;
    }

    float res[VEC];
    #pragma unroll
    for (int v = 0; v < VEC; v++) {
        float val = num[v] / den;
        if (bias) val += bias[ch0 + v];
        if (pre) val += pre[(size_t)dst * D + ch0 + v];
        if (RELU) val = fmaxf(val, 0.f);
        res[v] = val;
    }
    if (VEC == 2)
        *(float2*)&out[(size_t)dst * D + ch0] = make_float2(res[0], res[1]);
    else
        out[(size_t)dst * D + ch0] = res[0];
}

// ---------------- host launcher ----------------
extern "C" void kernel_launch(void* const* d_in, const int* in_sizes, int n_in,
                              void* d_out, int out_size) {
    const float* x     = (const float*)d_in[0];
    const int*   eidx  = (const int*)d_in[1];
    const float* eattr = (const float*)d_in[2];
    const float* Wl1 = (const float*)d_in[3];
    const float* bl1 = (const float*)d_in[4];
    const float* Wr1 = (const float*)d_in[5];
    const float* br1 = (const float*)d_in[6];
    const float* We1 = (const float*)d_in[7];
    const float* att1 = (const float*)d_in[8];
    const float* b1 = (const float*)d_in[9];
    const float* Wl2 = (const float*)d_in[10];
    const float* bl2 = (const float*)d_in[11];
    const float* Wr2 = (const float*)d_in[12];
    const float* br2 = (const float*)d_in[13];
    const float* We2 = (const float*)d_in[14];
    const float* att2 = (const float*)d_in[15];
    const float* b2 = (const float*)d_in[16];
    const float* Rw2 = (const float*)d_in[17];
    const float* Wl3 = (const float*)d_in[18];
    const float* bl3 = (const float*)d_in[19];
    const float* Wr3 = (const float*)d_in[20];
    const float* br3 = (const float*)d_in[21];
    const float* We3 = (const float*)d_in[22];
    const float* att3 = (const float*)d_in[23];
    const float* b3 = (const float*)d_in[24];

    int Nn = in_sizes[0] / 16;   // 50000
    int Ee = in_sizes[1] / 2;    // 800000
    const int* srcp = eidx;
    const int* dstp = eidx + Ee;

    float *xl, *xr, *res, *h1, *h2, *loopw, *eaP;
    int *deg, *rowptr, *wptr, *bsum, *colsrc;
    cudaGetSymbolAddress((void**)&xl, g_xl);
    cudaGetSymbolAddress((void**)&xr, g_xr);
    cudaGetSymbolAddress((void**)&res, g_res);
    cudaGetSymbolAddress((void**)&h1, g_h1);
    cudaGetSymbolAddress((void**)&h2, g_h2);
    cudaGetSymbolAddress((void**)&loopw, g_loop);
    cudaGetSymbolAddress((void**)&eaP, g_eaP);
    cudaGetSymbolAddress((void**)&deg, g_deg);
    cudaGetSymbolAddress((void**)&rowptr, g_rowptr);
    cudaGetSymbolAddress((void**)&wptr, g_wptr);
    cudaGetSymbolAddress((void**)&bsum, g_bsum);
    cudaGetSymbolAddress((void**)&colsrc, g_colsrc);

    int G = (Nn + 1023) / 1024;  // 49

    // ---- CSR + permuted eattr + self-loop attr ----
    cudaMemsetAsync(deg, 0, Nn * sizeof(int));
    hist_kernel<<<(Ee + 255) / 256, 256>>>(dstp, deg, Ee);
    blocksum_kernel<<<G, 1024>>>(deg, bsum, Nn);
    scanpart_kernel<<<1, 1024>>>(bsum, G);
    scanfinal_kernel<<<G, 1024>>>(deg, bsum, rowptr, wptr, Nn, Ee);
    scatter_kernel<<<(Ee + 255) / 256, 256>>>(srcp, dstp, eattr, wptr, colsrc, eaP, Ee);
    loopattr_kernel<<<(Nn * 8 + 255) / 256, 256>>>(rowptr, eaP, loopw, Nn);

    // ---- layer 1: in=16 -> D=32 (H=4), relu ----
    gemm_multi<16, 32, 2, 32, 16><<<(Nn + 31) / 32, 128>>>(
        x, Wl1, bl1, xl, Wr1, br1, xr, nullptr, nullptr, nullptr, Nn);
    agg_kernel<1, 1, 8, true><<<(Nn + 7) / 8, 256>>>(
        xl, xr, eaP, We1, att1, b1, nullptr, rowptr, colsrc, loopw, h1, Nn);

    // ---- layer 2: in=32 -> D=128 (H=4), residual h1@Rw2 + b2, relu (3 GEMMs fused) ----
    gemm_multi<32, 128, 3, 16, 32><<<(Nn + 15) / 16, 384>>>(
        h1, Wl2, bl2, xl, Wr2, br2, xr, Rw2, b2, res, Nn);
    agg_kernel<2, 2, 16, true><<<(Nn + 3) / 4, 256>>>(
        xl, xr, eaP, We2, att2, nullptr, res, rowptr, colsrc, loopw, h2, Nn);

    // ---- layer 3: in=128 -> D=32 (H=1), no relu ----
    gemm_multi<128, 32, 2, 32, 32><<<(Nn + 31) / 32, 128>>>(
        h2, Wl3, bl3, xl, Wr3, br3, xr, nullptr, nullptr, nullptr, Nn);
    agg_kernel<1, 1, 32, false><<<(Nn + 7) / 8, 256>>>(
        xl, xr, eaP, We3, att3, b3, nullptr, rowptr, colsrc, loopw, (float*)d_out, Nn);
}